// round 1
// baseline (speedup 1.0000x reference)
#include <cuda_runtime.h>
#include <math.h>

#define NB      32
#define T_IN    512
#define NEW_T   426
#define NCC     1629            // N*C = 543*3
#define JF      53              // JITTER_FREQ
#define X_ELEMS (NB*NEW_T*NCC)  // 22,205,088

// Per-(b,t) table: x = idx0 (or -1.0f if frame kept), y = idx1, z = drop-interp frac, w = jitter
__device__ float4 g_tab[NB * NEW_T];

__device__ __forceinline__ int read_bool(const void* p, int mode, int i) {
    if (mode == 0) return ((const unsigned char*)p)[i] != 0;
    if (mode == 1) return ((const int*)p)[i] != 0;
    return ((const float*)p)[i] != 0.0f;
}

// Probe encoding of a bool buffer using an element KNOWN to be true.
// u8 storage: byte[idx]==1.  i32/f32 storage of 0/1: byte[idx] (idx%4!=0 chosen)==0.
__device__ __forceinline__ int probe_mode(const void* p, int known_true_idx) {
    if (((const unsigned char*)p)[known_true_idx] != 0) return 0;   // u8
    if (((const int*)p)[known_true_idx] == 1) return 1;             // i32
    return 2;                                                       // f32
}

__global__ void setup_kernel(const void* __restrict__ mask,
                             const void* __restrict__ keep,
                             const float* __restrict__ bj,
                             float* __restrict__ out, int write_mask)
{
    __shared__ int   s_scan[512];
    __shared__ short s_kept[NEW_T];
    int b = blockIdx.x;
    int t = threadIdx.x;

    // keep_mask[:, -1] is forced True by the reference setup -> element 425 of row 0
    // is a valid probe; byte offset 425 has 425%4==1, so the probe is unambiguous.
    int bmode = probe_mode(keep, NEW_T - 1);

    int kv = (t < NEW_T) ? read_bool(keep, bmode, b * NEW_T + t) : 0;
    s_scan[t] = kv;
    // Hillis-Steele inclusive scan over 512 slots
    for (int off = 1; off < 512; off <<= 1) {
        __syncthreads();
        int v = s_scan[t];
        int add = (t >= off) ? s_scan[t - off] : 0;
        __syncthreads();
        s_scan[t] = v + add;
    }
    __syncthreads();
    int K = s_scan[NEW_T - 1];
    if (t < NEW_T && kv) s_kept[s_scan[t] - 1] = (short)t;   // stable kept-index list == argsort trick
    __syncthreads();

    if (t < NEW_T) {
        // drop re-interpolation indices:  s = t*(K-1)/425 in fp32 (mul then div, as in jax)
        float s  = (float)t * (float)(K - 1) / 425.0f;
        int  r0  = (int)floorf(s);
        if (r0 < 0) r0 = 0;
        if (r0 > K - 2) r0 = K - 2;
        float fr = s - (float)r0;

        float4 tb;
        if (kv) { tb.x = -1.0f; tb.y = 0.0f; tb.z = 0.0f; }
        else    { tb.x = (float)s_kept[r0]; tb.y = (float)s_kept[r0 + 1]; tb.z = fr; }

        // jitter resample 53 -> 426, align_corners
        float sj = (float)t * (float)(52.0 / 425.0);
        int  j0  = (int)floorf(sj);
        if (j0 > JF - 2) j0 = JF - 2;
        float fj = sj - (float)j0;
        tb.w = (bj[b * JF + j0] * 0.02f) * (1.0f - fj) + (bj[b * JF + j0 + 1] * 0.02f) * fj;

        g_tab[b * NEW_T + t] = tb;

        if (write_mask) {
            float nf = (float)t * (float)(512.0 / 426.0);
            int ni = (int)floorf(nf);
            if (ni > T_IN - 1) ni = T_IN - 1;
            int m = read_bool(mask, bmode, b * T_IN + ni);   // same encoding as keep_mask
            out[X_ELEMS + b * NEW_T + t] = (m && kv) ? 1.0f : 0.0f;
        }
    }
}

__global__ void __launch_bounds__(256)
main_kernel(const float* __restrict__ x, const float* __restrict__ noise,
            const float* __restrict__ sp, float* __restrict__ out)
{
    int idx = blockIdx.x * blockDim.x + threadIdx.x;
    if (idx >= X_ELEMS) return;
    int b  = idx / (NEW_T * NCC);
    int r  = idx - b * (NEW_T * NCC);
    int t  = r / NCC;
    int nc = r - t * NCC;

    const float* xb = x + (size_t)b * T_IN * NCC;

    // time resample 512 -> 426 at resampled index tt (align_corners)
    auto resamp = [&](int tt) -> float {
        float s  = (float)tt * (float)(511.0 / 425.0);
        int  i0  = (int)s;                 // tt >= 0
        if (i0 > T_IN - 2) i0 = T_IN - 2;
        float f  = s - (float)i0;
        float a  = xb[i0 * NCC + nc];
        float c  = xb[(i0 + 1) * NCC + nc];
        return a * (1.0f - f) + c * f;
    };
    auto x2 = [&](const float4& tb, int tt) -> float {
        if (tb.x < 0.0f) return resamp(tt);
        return resamp((int)tb.x) * (1.0f - tb.z) + resamp((int)tb.y) * tb.z;
    };

    float4 tbt = g_tab[b * NEW_T + t];
    float cur = x2(tbt, t);
    float val;
    if (t == 0) {
        val = cur;
    } else {
        float4 tbp = g_tab[b * NEW_T + t - 1];
        float prev = x2(tbp, t - 1);
        val = cur + (cur - prev) * tbt.w;   // x + vel*jit
    }
    val += noise[idx] * 0.01f + sp[b * NCC + nc] * 0.005f;
    out[idx] = val;
}

extern "C" void kernel_launch(void* const* d_in, const int* in_sizes, int n_in,
                              void* d_out, int out_size)
{
    const float* x = nullptr; const void* mask = nullptr; const void* keep = nullptr;
    const float* bj = nullptr; const float* noise = nullptr; const float* sp = nullptr;

    // all six element counts are distinct -> bind by size, order-proof
    for (int i = 0; i < n_in; i++) {
        switch (in_sizes[i]) {
            case NB * T_IN * NCC:  x     = (const float*)d_in[i]; break;  // 26,738,688
            case NB * T_IN:        mask  = d_in[i];               break;  // 16,384
            case NB * NEW_T:       keep  = d_in[i];               break;  // 13,632
            case NB * JF:          bj    = (const float*)d_in[i]; break;  // 1,696
            case NB * NEW_T * NCC: noise = (const float*)d_in[i]; break;  // 22,205,088
            case NB * NCC:         sp    = (const float*)d_in[i]; break;  // 52,128
            default: break;
        }
    }

    int write_mask = (out_size >= X_ELEMS + NB * NEW_T) ? 1 : 0;
    setup_kernel<<<NB, 512>>>(mask, keep, bj, (float*)d_out, write_mask);
    main_kernel<<<(X_ELEMS + 255) / 256, 256>>>(x, noise, sp, (float*)d_out);
}

// round 3
// speedup vs baseline: 1.4003x; 1.4003x over previous
#include <cuda_runtime.h>
#include <math.h>

#define NB      32
#define T_IN    512
#define NEW_T   426
#define NCC     1629            // N*C = 543*3
#define JF      53              // JITTER_FREQ
#define X_ELEMS (NB*NEW_T*NCC)  // 22,205,088

// Per-(b,t) table: x = idx0 (or -1.0f if frame kept), y = idx1, z = drop-interp frac, w = jitter
__device__ float4 g_tab[NB * NEW_T];

__device__ __forceinline__ int read_bool(const void* p, int mode, int i) {
    if (mode == 0) return ((const unsigned char*)p)[i] != 0;
    if (mode == 1) return ((const int*)p)[i] != 0;
    return ((const float*)p)[i] != 0.0f;
}

// Probe encoding of a bool buffer using an element KNOWN to be true.
__device__ __forceinline__ int probe_mode(const void* p, int known_true_idx) {
    if (((const unsigned char*)p)[known_true_idx] != 0) return 0;   // u8
    if (((const int*)p)[known_true_idx] == 1) return 1;             // i32
    return 2;                                                       // f32
}

__global__ void setup_kernel(const void* __restrict__ mask,
                             const void* __restrict__ keep,
                             const float* __restrict__ bj,
                             float* __restrict__ out, int write_mask)
{
    __shared__ int   s_scan[512];
    __shared__ short s_kept[NEW_T];
    int b = blockIdx.x;
    int t = threadIdx.x;

    int bmode = probe_mode(keep, NEW_T - 1);

    int kv = (t < NEW_T) ? read_bool(keep, bmode, b * NEW_T + t) : 0;
    s_scan[t] = kv;
    for (int off = 1; off < 512; off <<= 1) {
        __syncthreads();
        int v = s_scan[t];
        int add = (t >= off) ? s_scan[t - off] : 0;
        __syncthreads();
        s_scan[t] = v + add;
    }
    __syncthreads();
    int K = s_scan[NEW_T - 1];
    if (t < NEW_T && kv) s_kept[s_scan[t] - 1] = (short)t;
    __syncthreads();

    if (t < NEW_T) {
        float s  = (float)t * (float)(K - 1) / 425.0f;
        int  r0  = (int)floorf(s);
        if (r0 < 0) r0 = 0;
        if (r0 > K - 2) r0 = K - 2;
        float fr = s - (float)r0;

        float4 tb;
        if (kv) { tb.x = -1.0f; tb.y = 0.0f; tb.z = 0.0f; }
        else    { tb.x = (float)s_kept[r0]; tb.y = (float)s_kept[r0 + 1]; tb.z = fr; }

        float sj = (float)t * (float)(52.0 / 425.0);
        int  j0  = (int)floorf(sj);
        if (j0 > JF - 2) j0 = JF - 2;
        float fj = sj - (float)j0;
        tb.w = (bj[b * JF + j0] * 0.02f) * (1.0f - fj) + (bj[b * JF + j0 + 1] * 0.02f) * fj;

        g_tab[b * NEW_T + t] = tb;

        if (write_mask) {
            float nf = (float)t * (float)(512.0 / 426.0);
            int ni = (int)floorf(nf);
            if (ni > T_IN - 1) ni = T_IN - 1;
            int m = read_bool(mask, bmode, b * T_IN + ni);
            out[X_ELEMS + b * NEW_T + t] = (m && kv) ? 1.0f : 0.0f;
        }
    }
}

struct Arm { int i0; float f; float w; };

__device__ __forceinline__ void ridx(int tt, int& i0, float& f) {
    float s = (float)tt * (float)(511.0 / 425.0);
    int i = (int)s;
    if (i > T_IN - 2) i = T_IN - 2;
    i0 = i;
    f = s - (float)i;
}

// Build the (up to 2) source arms for the post-drop signal at time tt.
__device__ __forceinline__ int mkarms(const float4& tb, int tt, Arm* a) {
    if (tb.x < 0.0f) {
        ridx(tt, a[0].i0, a[0].f); a[0].w = 1.0f;
        return 1;
    }
    ridx((int)tb.x, a[0].i0, a[0].f); a[0].w = 1.0f - tb.z;
    ridx((int)tb.y, a[1].i0, a[1].f); a[1].w = tb.z;
    return 2;
}

// One block per (b,t) row; each thread produces 4 contiguous nc elements.
// All row-level control (resample indices/fracs, arms, jitter) is uniform per block.
__global__ void __launch_bounds__(416)
main_kernel(const float* __restrict__ x, const float* __restrict__ noise,
            const float* __restrict__ sp, float* __restrict__ out)
{
    const int t = blockIdx.x;
    const int b = blockIdx.y;
    const int row = b * NEW_T + t;

    const int nc0 = threadIdx.x * 4;
    if (nc0 >= NCC) return;
    const int rem = NCC - nc0;                 // ==4 for all but last thread (NCC%4==1)
    const bool full = (rem >= 4);

    const float* __restrict__ xb = x + (size_t)b * T_IN * NCC;

    const float4 tbt = g_tab[row];
    Arm ca[2]; const int cn = mkarms(tbt, t, ca);
    Arm pa[2]; int pn = 0;
    if (t > 0) {
        const float4 tbp = g_tab[row - 1];
        pn = mkarms(tbp, t - 1, pa);
    }

    float cur[4]  = {0.f, 0.f, 0.f, 0.f};
    float prev[4] = {0.f, 0.f, 0.f, 0.f};

    if (full) {
        #pragma unroll
        for (int a = 0; a < 2; a++) {
            if (a < cn) {
                const float* p0 = xb + (size_t)ca[a].i0 * NCC + nc0;
                const float f = ca[a].f, w = ca[a].w;
                float v0[4], v1[4];
                #pragma unroll
                for (int k = 0; k < 4; k++) v0[k] = __ldg(p0 + k);
                #pragma unroll
                for (int k = 0; k < 4; k++) v1[k] = __ldg(p0 + NCC + k);
                #pragma unroll
                for (int k = 0; k < 4; k++)
                    cur[k] += w * (v0[k] * (1.0f - f) + v1[k] * f);
            }
        }
        #pragma unroll
        for (int a = 0; a < 2; a++) {
            if (a < pn) {
                const float* p0 = xb + (size_t)pa[a].i0 * NCC + nc0;
                const float f = pa[a].f, w = pa[a].w;
                float v0[4], v1[4];
                #pragma unroll
                for (int k = 0; k < 4; k++) v0[k] = __ldg(p0 + k);
                #pragma unroll
                for (int k = 0; k < 4; k++) v1[k] = __ldg(p0 + NCC + k);
                #pragma unroll
                for (int k = 0; k < 4; k++)
                    prev[k] += w * (v0[k] * (1.0f - f) + v1[k] * f);
            }
        }
        const float jit = tbt.w;
        const size_t oidx = (size_t)row * NCC + nc0;
        float nz[4], spv[4];
        #pragma unroll
        for (int k = 0; k < 4; k++) nz[k]  = __ldg(noise + oidx + k);
        #pragma unroll
        for (int k = 0; k < 4; k++) spv[k] = __ldg(sp + (size_t)b * NCC + nc0 + k);
        #pragma unroll
        for (int k = 0; k < 4; k++) {
            float v = (t == 0) ? cur[k] : cur[k] + (cur[k] - prev[k]) * jit;
            out[oidx + k] = v + nz[k] * 0.01f + spv[k] * 0.005f;
        }
    } else {
        // tail thread (rem = 1 since NCC % 4 == 1)
        for (int k = 0; k < rem; k++) {
            float c = 0.f, p = 0.f;
            for (int a = 0; a < cn; a++) {
                const float* p0 = xb + (size_t)ca[a].i0 * NCC + nc0 + k;
                c += ca[a].w * (__ldg(p0) * (1.0f - ca[a].f) + __ldg(p0 + NCC) * ca[a].f);
            }
            for (int a = 0; a < pn; a++) {
                const float* p0 = xb + (size_t)pa[a].i0 * NCC + nc0 + k;
                p += pa[a].w * (__ldg(p0) * (1.0f - pa[a].f) + __ldg(p0 + NCC) * pa[a].f);
            }
            const size_t oidx = (size_t)row * NCC + nc0 + k;
            float v = (t == 0) ? c : c + (c - p) * tbt.w;
            out[oidx] = v + __ldg(noise + oidx) * 0.01f
                          + __ldg(sp + (size_t)b * NCC + nc0 + k) * 0.005f;
        }
    }
}

extern "C" void kernel_launch(void* const* d_in, const int* in_sizes, int n_in,
                              void* d_out, int out_size)
{
    const float* x = nullptr; const void* mask = nullptr; const void* keep = nullptr;
    const float* bj = nullptr; const float* noise = nullptr; const float* sp = nullptr;

    for (int i = 0; i < n_in; i++) {
        switch (in_sizes[i]) {
            case NB * T_IN * NCC:  x     = (const float*)d_in[i]; break;
            case NB * T_IN:        mask  = d_in[i];               break;
            case NB * NEW_T:       keep  = d_in[i];               break;
            case NB * JF:          bj    = (const float*)d_in[i]; break;
            case NB * NEW_T * NCC: noise = (const float*)d_in[i]; break;
            case NB * NCC:         sp    = (const float*)d_in[i]; break;
            default: break;
        }
    }

    int write_mask = (out_size >= X_ELEMS + NB * NEW_T) ? 1 : 0;
    setup_kernel<<<NB, 512>>>(mask, keep, bj, (float*)d_out, write_mask);
    dim3 grid(NEW_T, NB);
    main_kernel<<<grid, 416>>>(x, noise, sp, (float*)d_out);
}

// round 4
// speedup vs baseline: 1.6460x; 1.1755x over previous
#include <cuda_runtime.h>
#include <math.h>

#define NB      32
#define T_IN    512
#define NEW_T   426
#define NCC     1629            // N*C = 543*3
#define JF      53              // JITTER_FREQ
#define X_ELEMS (NB*NEW_T*NCC)  // 22,205,088
#define BTHREADS 416            // 416*4 = 1664 >= 1629

// Per-(b,t) table: x = idx0 (or -1.0f if frame kept), y = idx1, z = drop-interp frac, w = jitter
__device__ float4 g_tab[NB * NEW_T];

__device__ __forceinline__ int read_bool(const void* p, int mode, int i) {
    if (mode == 0) return ((const unsigned char*)p)[i] != 0;
    if (mode == 1) return ((const int*)p)[i] != 0;
    return ((const float*)p)[i] != 0.0f;
}

__device__ __forceinline__ int probe_mode(const void* p, int known_true_idx) {
    if (((const unsigned char*)p)[known_true_idx] != 0) return 0;   // u8
    if (((const int*)p)[known_true_idx] == 1) return 1;             // i32
    return 2;                                                       // f32
}

__global__ void setup_kernel(const void* __restrict__ mask,
                             const void* __restrict__ keep,
                             const float* __restrict__ bj,
                             float* __restrict__ out, int write_mask)
{
    __shared__ int   s_scan[512];
    __shared__ short s_kept[NEW_T];
    int b = blockIdx.x;
    int t = threadIdx.x;

    int bmode = probe_mode(keep, NEW_T - 1);

    int kv = (t < NEW_T) ? read_bool(keep, bmode, b * NEW_T + t) : 0;
    s_scan[t] = kv;
    for (int off = 1; off < 512; off <<= 1) {
        __syncthreads();
        int v = s_scan[t];
        int add = (t >= off) ? s_scan[t - off] : 0;
        __syncthreads();
        s_scan[t] = v + add;
    }
    __syncthreads();
    int K = s_scan[NEW_T - 1];
    if (t < NEW_T && kv) s_kept[s_scan[t] - 1] = (short)t;
    __syncthreads();

    if (t < NEW_T) {
        float s  = (float)t * (float)(K - 1) / 425.0f;
        int  r0  = (int)floorf(s);
        if (r0 < 0) r0 = 0;
        if (r0 > K - 2) r0 = K - 2;
        float fr = s - (float)r0;

        float4 tb;
        if (kv) { tb.x = -1.0f; tb.y = 0.0f; tb.z = 0.0f; }
        else    { tb.x = (float)s_kept[r0]; tb.y = (float)s_kept[r0 + 1]; tb.z = fr; }

        float sj = (float)t * (float)(52.0 / 425.0);
        int  j0  = (int)floorf(sj);
        if (j0 > JF - 2) j0 = JF - 2;
        float fj = sj - (float)j0;
        tb.w = (bj[b * JF + j0] * 0.02f) * (1.0f - fj) + (bj[b * JF + j0 + 1] * 0.02f) * fj;

        g_tab[b * NEW_T + t] = tb;

        if (write_mask) {
            float nf = (float)t * (float)(512.0 / 426.0);
            int ni = (int)floorf(nf);
            if (ni > T_IN - 1) ni = T_IN - 1;
            int m = read_bool(mask, bmode, b * T_IN + ni);
            out[X_ELEMS + b * NEW_T + t] = (m && kv) ? 1.0f : 0.0f;
        }
    }
}

struct Arm { int i0; float f; float w; };

__device__ __forceinline__ void ridx(int tt, int& i0, float& f) {
    float s = (float)tt * (float)(511.0 / 425.0);
    int i = (int)s;
    if (i > T_IN - 2) i = T_IN - 2;
    i0 = i;
    f = s - (float)i;
}

__device__ __forceinline__ int mkarms(const float4& tb, int tt, Arm* a) {
    if (tb.x < 0.0f) {
        ridx(tt, a[0].i0, a[0].f); a[0].w = 1.0f;
        return 1;
    }
    ridx((int)tb.x, a[0].i0, a[0].f); a[0].w = 1.0f - tb.z;
    ridx((int)tb.y, a[1].i0, a[1].f); a[1].w = tb.z;
    return 2;
}

// One block per (b,t) row; thread tid handles elements {tid + k*416}, k=0..3
// -> every LDG.32 is fully coalesced (1 line/warp) while keeping 4-way ILP.
__global__ void __launch_bounds__(BTHREADS)
main_kernel(const float* __restrict__ x, const float* __restrict__ noise,
            const float* __restrict__ sp, float* __restrict__ out)
{
    const int t = blockIdx.x;
    const int b = blockIdx.y;
    const int row = b * NEW_T + t;
    const int tid = threadIdx.x;

    const float* __restrict__ xb = x + (size_t)b * T_IN * NCC;

    const float4 tbt = g_tab[row];
    Arm ca[2]; const int cn = mkarms(tbt, t, ca);
    Arm pa[2]; int pn = 0;
    if (t > 0) {
        const float4 tbp = g_tab[row - 1];
        pn = mkarms(tbp, t - 1, pa);
    }

    bool valid[4];
    int  nc[4];
    #pragma unroll
    for (int k = 0; k < 4; k++) {
        nc[k] = tid + k * BTHREADS;
        valid[k] = (nc[k] < NCC);
    }

    float cur[4]  = {0.f, 0.f, 0.f, 0.f};
    float prev[4] = {0.f, 0.f, 0.f, 0.f};

    #pragma unroll
    for (int a = 0; a < 2; a++) {
        if (a < cn) {
            const float* p0 = xb + (size_t)ca[a].i0 * NCC;
            const float f = ca[a].f, w = ca[a].w;
            float v0[4], v1[4];
            #pragma unroll
            for (int k = 0; k < 4; k++) if (valid[k]) v0[k] = __ldg(p0 + nc[k]);
            #pragma unroll
            for (int k = 0; k < 4; k++) if (valid[k]) v1[k] = __ldg(p0 + NCC + nc[k]);
            #pragma unroll
            for (int k = 0; k < 4; k++) if (valid[k])
                cur[k] += w * (v0[k] * (1.0f - f) + v1[k] * f);
        }
    }
    #pragma unroll
    for (int a = 0; a < 2; a++) {
        if (a < pn) {
            const float* p0 = xb + (size_t)pa[a].i0 * NCC;
            const float f = pa[a].f, w = pa[a].w;
            float v0[4], v1[4];
            #pragma unroll
            for (int k = 0; k < 4; k++) if (valid[k]) v0[k] = __ldg(p0 + nc[k]);
            #pragma unroll
            for (int k = 0; k < 4; k++) if (valid[k]) v1[k] = __ldg(p0 + NCC + nc[k]);
            #pragma unroll
            for (int k = 0; k < 4; k++) if (valid[k])
                prev[k] += w * (v0[k] * (1.0f - f) + v1[k] * f);
        }
    }

    const float jit = tbt.w;
    const size_t rbase = (size_t)row * NCC;
    const size_t sbase = (size_t)b * NCC;
    float nz[4], spv[4];
    #pragma unroll
    for (int k = 0; k < 4; k++) if (valid[k]) nz[k]  = __ldg(noise + rbase + nc[k]);
    #pragma unroll
    for (int k = 0; k < 4; k++) if (valid[k]) spv[k] = __ldg(sp + sbase + nc[k]);
    #pragma unroll
    for (int k = 0; k < 4; k++) {
        if (valid[k]) {
            float v = (t == 0) ? cur[k] : cur[k] + (cur[k] - prev[k]) * jit;
            out[rbase + nc[k]] = v + nz[k] * 0.01f + spv[k] * 0.005f;
        }
    }
}

extern "C" void kernel_launch(void* const* d_in, const int* in_sizes, int n_in,
                              void* d_out, int out_size)
{
    const float* x = nullptr; const void* mask = nullptr; const void* keep = nullptr;
    const float* bj = nullptr; const float* noise = nullptr; const float* sp = nullptr;

    for (int i = 0; i < n_in; i++) {
        switch (in_sizes[i]) {
            case NB * T_IN * NCC:  x     = (const float*)d_in[i]; break;
            case NB * T_IN:        mask  = d_in[i];               break;
            case NB * NEW_T:       keep  = d_in[i];               break;
            case NB * JF:          bj    = (const float*)d_in[i]; break;
            case NB * NEW_T * NCC: noise = (const float*)d_in[i]; break;
            case NB * NCC:         sp    = (const float*)d_in[i]; break;
            default: break;
        }
    }

    int write_mask = (out_size >= X_ELEMS + NB * NEW_T) ? 1 : 0;
    setup_kernel<<<NB, 512>>>(mask, keep, bj, (float*)d_out, write_mask);
    dim3 grid(NEW_T, NB);
    main_kernel<<<grid, BTHREADS>>>(x, noise, sp, (float*)d_out);
}

// round 6
// speedup vs baseline: 2.1548x; 1.3091x over previous
#include <cuda_runtime.h>
#include <math.h>

#define NB      32
#define T_IN    512
#define NEW_T   426
#define NCC     1629            // N*C = 543*3
#define JF      53              // JITTER_FREQ
#define X_ELEMS (NB*NEW_T*NCC)  // 22,205,088
#define BTHREADS 416            // 416*4 = 1664 >= 1629
#define RROWS   6               // 426 = 71 * 6

// Per-(b,t) table: x = idx0 (or -1.0f if frame kept), y = idx1, z = drop-interp frac, w = jitter
__device__ float4 g_tab[NB * NEW_T];

__device__ __forceinline__ int read_bool(const void* p, int mode, int i) {
    if (mode == 0) return ((const unsigned char*)p)[i] != 0;
    if (mode == 1) return ((const int*)p)[i] != 0;
    return ((const float*)p)[i] != 0.0f;
}

__device__ __forceinline__ int probe_mode(const void* p, int known_true_idx) {
    if (((const unsigned char*)p)[known_true_idx] != 0) return 0;   // u8
    if (((const int*)p)[known_true_idx] == 1) return 1;             // i32
    return 2;                                                       // f32
}

__global__ void setup_kernel(const void* __restrict__ mask,
                             const void* __restrict__ keep,
                             const float* __restrict__ bj,
                             float* __restrict__ out, int write_mask)
{
    __shared__ int   s_scan[512];
    __shared__ short s_kept[NEW_T];
    int b = blockIdx.x;
    int t = threadIdx.x;

    int bmode = probe_mode(keep, NEW_T - 1);

    int kv = (t < NEW_T) ? read_bool(keep, bmode, b * NEW_T + t) : 0;
    s_scan[t] = kv;
    for (int off = 1; off < 512; off <<= 1) {
        __syncthreads();
        int v = s_scan[t];
        int add = (t >= off) ? s_scan[t - off] : 0;
        __syncthreads();
        s_scan[t] = v + add;
    }
    __syncthreads();
    int K = s_scan[NEW_T - 1];
    if (t < NEW_T && kv) s_kept[s_scan[t] - 1] = (short)t;
    __syncthreads();

    if (t < NEW_T) {
        float s  = (float)t * (float)(K - 1) / 425.0f;
        int  r0  = (int)floorf(s);
        if (r0 < 0) r0 = 0;
        if (r0 > K - 2) r0 = K - 2;
        float fr = s - (float)r0;

        float4 tb;
        if (kv) { tb.x = -1.0f; tb.y = 0.0f; tb.z = 0.0f; }
        else    { tb.x = (float)s_kept[r0]; tb.y = (float)s_kept[r0 + 1]; tb.z = fr; }

        float sj = (float)t * (float)(52.0 / 425.0);
        int  j0  = (int)floorf(sj);
        if (j0 > JF - 2) j0 = JF - 2;
        float fj = sj - (float)j0;
        tb.w = (bj[b * JF + j0] * 0.02f) * (1.0f - fj) + (bj[b * JF + j0 + 1] * 0.02f) * fj;

        g_tab[b * NEW_T + t] = tb;

        if (write_mask) {
            float nf = (float)t * (float)(512.0 / 426.0);
            int ni = (int)floorf(nf);
            if (ni > T_IN - 1) ni = T_IN - 1;
            int m = read_bool(mask, bmode, b * T_IN + ni);
            out[X_ELEMS + b * NEW_T + t] = (m && kv) ? 1.0f : 0.0f;
        }
    }
}

struct Arm { int i0; float f; float w; };

__device__ __forceinline__ void ridx(int tt, int& i0, float& f) {
    float s = (float)tt * (float)(511.0 / 425.0);
    int i = (int)s;
    if (i > T_IN - 2) i = T_IN - 2;
    i0 = i;
    f = s - (float)i;
}

__device__ __forceinline__ int mkarms(const float4& tb, int tt, Arm* a) {
    if (tb.x < 0.0f) {
        ridx(tt, a[0].i0, a[0].f); a[0].w = 1.0f;
        return 1;
    }
    ridx((int)tb.x, a[0].i0, a[0].f); a[0].w = 1.0f - tb.z;
    ridx((int)tb.y, a[1].i0, a[1].f); a[1].w = tb.z;
    return 2;
}

// Compute the post-drop signal x2 at time tt for 4 strided nc elements.
__device__ __forceinline__ void compute_x2(const float4& tb, int tt,
                                           const float* __restrict__ xb,
                                           const int* nc, const bool* valid,
                                           float* o)
{
    Arm a[2];
    const int n = mkarms(tb, tt, a);
    #pragma unroll
    for (int k = 0; k < 4; k++) o[k] = 0.f;
    #pragma unroll
    for (int ai = 0; ai < 2; ai++) {
        if (ai < n) {                              // block-uniform branch
            const float* p0 = xb + (size_t)a[ai].i0 * NCC;
            const float f = a[ai].f, w = a[ai].w;
            float v0[4], v1[4];
            #pragma unroll
            for (int k = 0; k < 4; k++) if (valid[k]) v0[k] = __ldg(p0 + nc[k]);
            #pragma unroll
            for (int k = 0; k < 4; k++) if (valid[k]) v1[k] = __ldg(p0 + NCC + nc[k]);
            #pragma unroll
            for (int k = 0; k < 4; k++) if (valid[k])
                o[k] += w * (v0[k] * (1.0f - f) + v1[k] * f);
        }
    }
}

// One block per (b, 6-row time strip). cur rolls into prev so each x2 is
// computed once; sp loaded once per block; next tab prefetched.
__global__ void __launch_bounds__(BTHREADS)
main_kernel(const float* __restrict__ x, const float* __restrict__ noise,
            const float* __restrict__ sp, float* __restrict__ out)
{
    const int t0 = blockIdx.x * RROWS;
    const int b  = blockIdx.y;
    const int row0 = b * NEW_T + t0;
    const int tid = threadIdx.x;

    const float* __restrict__ xb = x + (size_t)b * T_IN * NCC;

    bool valid[4];
    int  nc[4];
    #pragma unroll
    for (int k = 0; k < 4; k++) {
        nc[k] = tid + k * BTHREADS;
        valid[k] = (nc[k] < NCC);
    }

    // sp: loaded once per block, reused across all 6 rows
    const size_t sbase = (size_t)b * NCC;
    float spv[4];
    #pragma unroll
    for (int k = 0; k < 4; k++) if (valid[k]) spv[k] = __ldg(sp + sbase + nc[k]);

    // prev = x2(t0-1) (only needed when t0 > 0)
    float prev[4] = {0.f, 0.f, 0.f, 0.f};
    if (t0 > 0) {
        const float4 tbp = g_tab[row0 - 1];
        compute_x2(tbp, t0 - 1, xb, nc, valid, prev);
    }

    float4 tb = g_tab[row0];

    #pragma unroll 2
    for (int i = 0; i < RROWS; i++) {
        const int t = t0 + i;
        const int row = row0 + i;

        // prefetch next row's table entry
        float4 tb_nx;
        if (i + 1 < RROWS) tb_nx = g_tab[row + 1];

        float cur[4];
        compute_x2(tb, t, xb, nc, valid, cur);

        const size_t rbase = (size_t)row * NCC;
        float nz[4];
        #pragma unroll
        for (int k = 0; k < 4; k++) if (valid[k]) nz[k] = __ldg(noise + rbase + nc[k]);

        const float jit = tb.w;
        #pragma unroll
        for (int k = 0; k < 4; k++) {
            if (valid[k]) {
                float v = (t == 0) ? cur[k] : cur[k] + (cur[k] - prev[k]) * jit;
                out[rbase + nc[k]] = v + nz[k] * 0.01f + spv[k] * 0.005f;
            }
        }

        #pragma unroll
        for (int k = 0; k < 4; k++) prev[k] = cur[k];
        tb = tb_nx;
    }
}

extern "C" void kernel_launch(void* const* d_in, const int* in_sizes, int n_in,
                              void* d_out, int out_size)
{
    const float* x = nullptr; const void* mask = nullptr; const void* keep = nullptr;
    const float* bj = nullptr; const float* noise = nullptr; const float* sp = nullptr;

    for (int i = 0; i < n_in; i++) {
        switch (in_sizes[i]) {
            case NB * T_IN * NCC:  x     = (const float*)d_in[i]; break;
            case NB * T_IN:        mask  = d_in[i];               break;
            case NB * NEW_T:       keep  = d_in[i];               break;
            case NB * JF:          bj    = (const float*)d_in[i]; break;
            case NB * NEW_T * NCC: noise = (const float*)d_in[i]; break;
            case NB * NCC:         sp    = (const float*)d_in[i]; break;
            default: break;
        }
    }

    int write_mask = (out_size >= X_ELEMS + NB * NEW_T) ? 1 : 0;
    setup_kernel<<<NB, 512>>>(mask, keep, bj, (float*)d_out, write_mask);
    dim3 grid(NEW_T / RROWS, NB);   // 71 x 32
    main_kernel<<<grid, BTHREADS>>>(x, noise, sp, (float*)d_out);
}

// round 7
// speedup vs baseline: 2.4350x; 1.1300x over previous
#include <cuda_runtime.h>
#include <math.h>

#define NB      32
#define T_IN    512
#define NEW_T   426
#define NCC     1629            // N*C = 543*3
#define JF      53              // JITTER_FREQ
#define X_ELEMS (NB*NEW_T*NCC)  // 22,205,088
#define BTHREADS 416            // 416*4 = 1664 >= 1629
#define RROWS   6               // 426 = 71 * 6

// Per-(b,t) table: x = idx0 (or -1.0f if frame kept), y = idx1, z = drop-interp frac, w = jitter
__device__ float4 g_tab[NB * NEW_T];

__device__ __forceinline__ int read_bool(const void* p, int mode, int i) {
    if (mode == 0) return ((const unsigned char*)p)[i] != 0;
    if (mode == 1) return ((const int*)p)[i] != 0;
    return ((const float*)p)[i] != 0.0f;
}

__device__ __forceinline__ int probe_mode(const void* p, int known_true_idx) {
    if (((const unsigned char*)p)[known_true_idx] != 0) return 0;   // u8
    if (((const int*)p)[known_true_idx] == 1) return 1;             // i32
    return 2;                                                       // f32
}

// 512 threads: warp-shuffle inclusive scan of keep bits (2 barriers total).
__global__ void setup_kernel(const void* __restrict__ mask,
                             const void* __restrict__ keep,
                             const float* __restrict__ bj,
                             float* __restrict__ out, int write_mask)
{
    __shared__ int   s_wsum[16];
    __shared__ short s_kept[NEW_T];
    __shared__ int   s_K;
    int b = blockIdx.x;
    int t = threadIdx.x;
    int lane = t & 31, warp = t >> 5;

    int bmode = probe_mode(keep, NEW_T - 1);

    int kv = (t < NEW_T) ? read_bool(keep, bmode, b * NEW_T + t) : 0;

    // warp inclusive scan
    int v = kv;
    #pragma unroll
    for (int off = 1; off < 32; off <<= 1) {
        int n = __shfl_up_sync(0xffffffffu, v, off);
        if (lane >= off) v += n;
    }
    if (lane == 31) s_wsum[warp] = v;
    __syncthreads();
    if (warp == 0 && lane < 16) {
        int w = s_wsum[lane];
        #pragma unroll
        for (int off = 1; off < 16; off <<= 1) {
            int n = __shfl_up_sync(0xffffu, w, off);
            if (lane >= off) w += n;
        }
        s_wsum[lane] = w;
        if (lane == 13) s_K = w;   // warp 13 covers threads 416..447 >= t=425
    }
    __syncthreads();
    int incl = v + (warp > 0 ? s_wsum[warp - 1] : 0);
    // K = inclusive sum at t = NEW_T-1 = 425 (within warp 13)
    int K = s_K;
    if (t < NEW_T && kv) s_kept[incl - 1] = (short)t;
    __syncthreads();

    if (t < NEW_T) {
        float s  = (float)t * (float)(K - 1) / 425.0f;
        int  r0  = (int)floorf(s);
        if (r0 < 0) r0 = 0;
        if (r0 > K - 2) r0 = K - 2;
        float fr = s - (float)r0;

        float4 tb;
        if (kv) { tb.x = -1.0f; tb.y = 0.0f; tb.z = 0.0f; }
        else    { tb.x = (float)s_kept[r0]; tb.y = (float)s_kept[r0 + 1]; tb.z = fr; }

        float sj = (float)t * (float)(52.0 / 425.0);
        int  j0  = (int)floorf(sj);
        if (j0 > JF - 2) j0 = JF - 2;
        float fj = sj - (float)j0;
        tb.w = (bj[b * JF + j0] * 0.02f) * (1.0f - fj) + (bj[b * JF + j0 + 1] * 0.02f) * fj;

        g_tab[b * NEW_T + t] = tb;

        if (write_mask) {
            float nf = (float)t * (float)(512.0 / 426.0);
            int ni = (int)floorf(nf);
            if (ni > T_IN - 1) ni = T_IN - 1;
            int m = read_bool(mask, bmode, b * T_IN + ni);
            out[X_ELEMS + b * NEW_T + t] = (m && kv) ? 1.0f : 0.0f;
        }
    }
}

struct Arm { int i0; float f; float w; };

__device__ __forceinline__ void ridx(int tt, int& i0, float& f) {
    float s = (float)tt * (float)(511.0 / 425.0);
    int i = (int)s;
    if (i > T_IN - 2) i = T_IN - 2;
    i0 = i;
    f = s - (float)i;
}

__device__ __forceinline__ int mkarms(const float4& tb, int tt, Arm* a) {
    if (tb.x < 0.0f) {
        ridx(tt, a[0].i0, a[0].f); a[0].w = 1.0f;
        return 1;
    }
    ridx((int)tb.x, a[0].i0, a[0].f); a[0].w = 1.0f - tb.z;
    ridx((int)tb.y, a[1].i0, a[1].f); a[1].w = tb.z;
    return 2;
}

__device__ __forceinline__ void compute_x2(const float4& tb, int tt,
                                           const float* __restrict__ xb,
                                           const int* nc, const bool* valid,
                                           float* o)
{
    Arm a[2];
    const int n = mkarms(tb, tt, a);
    #pragma unroll
    for (int k = 0; k < 4; k++) o[k] = 0.f;
    #pragma unroll
    for (int ai = 0; ai < 2; ai++) {
        if (ai < n) {                              // block-uniform branch
            const float* p0 = xb + (size_t)a[ai].i0 * NCC;
            const float f = a[ai].f, w = a[ai].w;
            float v0[4], v1[4];
            #pragma unroll
            for (int k = 0; k < 4; k++) if (valid[k]) v0[k] = __ldg(p0 + nc[k]);
            #pragma unroll
            for (int k = 0; k < 4; k++) if (valid[k]) v1[k] = __ldg(p0 + NCC + nc[k]);
            #pragma unroll
            for (int k = 0; k < 4; k++) if (valid[k])
                o[k] += w * (v0[k] * (1.0f - f) + v1[k] * f);
        }
    }
}

// One block per (b, 6-row time strip); __launch_bounds__(416,4) => 52 warps/SM.
__global__ void __launch_bounds__(BTHREADS, 4)
main_kernel(const float* __restrict__ x, const float* __restrict__ noise,
            const float* __restrict__ sp, float* __restrict__ out)
{
    const int t0 = blockIdx.x * RROWS;
    const int b  = blockIdx.y;
    const int row0 = b * NEW_T + t0;
    const int tid = threadIdx.x;

    const float* __restrict__ xb = x + (size_t)b * T_IN * NCC;

    bool valid[4];
    int  nc[4];
    #pragma unroll
    for (int k = 0; k < 4; k++) {
        nc[k] = tid + k * BTHREADS;
        valid[k] = (nc[k] < NCC);
    }

    const size_t sbase = (size_t)b * NCC;
    float spv[4];
    #pragma unroll
    for (int k = 0; k < 4; k++) if (valid[k]) spv[k] = __ldg(sp + sbase + nc[k]);

    float prev[4] = {0.f, 0.f, 0.f, 0.f};
    if (t0 > 0) {
        const float4 tbp = g_tab[row0 - 1];
        compute_x2(tbp, t0 - 1, xb, nc, valid, prev);
    }

    float4 tb = g_tab[row0];

    #pragma unroll 3
    for (int i = 0; i < RROWS; i++) {
        const int t = t0 + i;
        const int row = row0 + i;

        float4 tb_nx;
        if (i + 1 < RROWS) tb_nx = g_tab[row + 1];

        float cur[4];
        compute_x2(tb, t, xb, nc, valid, cur);

        const size_t rbase = (size_t)row * NCC;
        float nz[4];
        #pragma unroll
        for (int k = 0; k < 4; k++) if (valid[k]) nz[k] = __ldg(noise + rbase + nc[k]);

        const float jit = tb.w;
        #pragma unroll
        for (int k = 0; k < 4; k++) {
            if (valid[k]) {
                float v = (t == 0) ? cur[k] : cur[k] + (cur[k] - prev[k]) * jit;
                out[rbase + nc[k]] = v + nz[k] * 0.01f + spv[k] * 0.005f;
            }
        }

        #pragma unroll
        for (int k = 0; k < 4; k++) prev[k] = cur[k];
        tb = tb_nx;
    }
}

extern "C" void kernel_launch(void* const* d_in, const int* in_sizes, int n_in,
                              void* d_out, int out_size)
{
    const float* x = nullptr; const void* mask = nullptr; const void* keep = nullptr;
    const float* bj = nullptr; const float* noise = nullptr; const float* sp = nullptr;

    for (int i = 0; i < n_in; i++) {
        switch (in_sizes[i]) {
            case NB * T_IN * NCC:  x     = (const float*)d_in[i]; break;
            case NB * T_IN:        mask  = d_in[i];               break;
            case NB * NEW_T:       keep  = d_in[i];               break;
            case NB * JF:          bj    = (const float*)d_in[i]; break;
            case NB * NEW_T * NCC: noise = (const float*)d_in[i]; break;
            case NB * NCC:         sp    = (const float*)d_in[i]; break;
            default: break;
        }
    }

    int write_mask = (out_size >= X_ELEMS + NB * NEW_T) ? 1 : 0;
    setup_kernel<<<NB, 512>>>(mask, keep, bj, (float*)d_out, write_mask);
    dim3 grid(NEW_T / RROWS, NB);   // 71 x 32
    main_kernel<<<grid, BTHREADS>>>(x, noise, sp, (float*)d_out);
}

// round 8
// speedup vs baseline: 2.6120x; 1.0727x over previous
#include <cuda_runtime.h>
#include <math.h>

#define NB      32
#define T_IN    512
#define NEW_T   426
#define NCC     1629            // N*C = 543*3
#define JF      53              // JITTER_FREQ
#define X_ELEMS (NB*NEW_T*NCC)  // 22,205,088
#define BTHREADS 416            // 416*4 = 1664 >= 1629
#define RROWS   6               // 426 = 71 * 6

// Per-(b,t) table: x = idx0 (or -1.0f if frame kept), y = idx1, z = drop-interp frac, w = jitter
__device__ float4 g_tab[NB * NEW_T];

__device__ __forceinline__ int read_bool(const void* p, int mode, int i) {
    if (mode == 0) return ((const unsigned char*)p)[i] != 0;
    if (mode == 1) return ((const int*)p)[i] != 0;
    return ((const float*)p)[i] != 0.0f;
}

__device__ __forceinline__ int probe_mode(const void* p, int known_true_idx) {
    if (((const unsigned char*)p)[known_true_idx] != 0) return 0;   // u8
    if (((const int*)p)[known_true_idx] == 1) return 1;             // i32
    return 2;                                                       // f32
}

// 512 threads: warp-shuffle inclusive scan of keep bits (2 barriers total).
__global__ void setup_kernel(const void* __restrict__ mask,
                             const void* __restrict__ keep,
                             const float* __restrict__ bj,
                             float* __restrict__ out, int write_mask)
{
    __shared__ int   s_wsum[16];
    __shared__ short s_kept[NEW_T];
    __shared__ int   s_K;
    int b = blockIdx.x;
    int t = threadIdx.x;
    int lane = t & 31, warp = t >> 5;

    int bmode = probe_mode(keep, NEW_T - 1);

    int kv = (t < NEW_T) ? read_bool(keep, bmode, b * NEW_T + t) : 0;

    int v = kv;
    #pragma unroll
    for (int off = 1; off < 32; off <<= 1) {
        int n = __shfl_up_sync(0xffffffffu, v, off);
        if (lane >= off) v += n;
    }
    if (lane == 31) s_wsum[warp] = v;
    __syncthreads();
    if (warp == 0 && lane < 16) {
        int w = s_wsum[lane];
        #pragma unroll
        for (int off = 1; off < 16; off <<= 1) {
            int n = __shfl_up_sync(0xffffu, w, off);
            if (lane >= off) w += n;
        }
        s_wsum[lane] = w;
        if (lane == 13) s_K = w;
    }
    __syncthreads();
    int incl = v + (warp > 0 ? s_wsum[warp - 1] : 0);
    int K = s_K;
    if (t < NEW_T && kv) s_kept[incl - 1] = (short)t;
    __syncthreads();

    if (t < NEW_T) {
        float s  = (float)t * (float)(K - 1) / 425.0f;
        int  r0  = (int)floorf(s);
        if (r0 < 0) r0 = 0;
        if (r0 > K - 2) r0 = K - 2;
        float fr = s - (float)r0;

        float4 tb;
        if (kv) { tb.x = -1.0f; tb.y = 0.0f; tb.z = 0.0f; }
        else    { tb.x = (float)s_kept[r0]; tb.y = (float)s_kept[r0 + 1]; tb.z = fr; }

        float sj = (float)t * (float)(52.0 / 425.0);
        int  j0  = (int)floorf(sj);
        if (j0 > JF - 2) j0 = JF - 2;
        float fj = sj - (float)j0;
        tb.w = (bj[b * JF + j0] * 0.02f) * (1.0f - fj) + (bj[b * JF + j0 + 1] * 0.02f) * fj;

        g_tab[b * NEW_T + t] = tb;

        if (write_mask) {
            float nf = (float)t * (float)(512.0 / 426.0);
            int ni = (int)floorf(nf);
            if (ni > T_IN - 1) ni = T_IN - 1;
            int m = read_bool(mask, bmode, b * T_IN + ni);
            out[X_ELEMS + b * NEW_T + t] = (m && kv) ? 1.0f : 0.0f;
        }
    }
}

__device__ __forceinline__ void ridx(int tt, int& i0, float& f) {
    float s = (float)tt * (float)(511.0 / 425.0);
    int i = (int)s;
    if (i > T_IN - 2) i = T_IN - 2;
    i0 = i;
    f = s - (float)i;
}

// Row metadata: arm0 (pipelined) + optional arm1 (loaded at consumption; rare).
struct RowMeta {
    const float* p0; float f0, w0;
    const float* p1; float f1, w1;
    bool two;
    float jit;
};

__device__ __forceinline__ RowMeta mkmeta(const float4& tb, int tt,
                                          const float* __restrict__ xb, bool zero_jit)
{
    RowMeta m;
    int i0; float f;
    if (tb.x < 0.0f) {
        ridx(tt, i0, f);
        m.p0 = xb + (size_t)i0 * NCC; m.f0 = f; m.w0 = 1.0f;
        m.two = false; m.p1 = m.p0; m.f1 = 0.f; m.w1 = 0.f;
    } else {
        ridx((int)tb.x, i0, f);
        m.p0 = xb + (size_t)i0 * NCC; m.f0 = f; m.w0 = 1.0f - tb.z;
        int i1; float f1; ridx((int)tb.y, i1, f1);
        m.p1 = xb + (size_t)i1 * NCC; m.f1 = f1; m.w1 = tb.z;
        m.two = true;
    }
    m.jit = zero_jit ? 0.0f : tb.w;
    return m;
}

// Issue arm-0 loads (8 LDGs) into registers.
__device__ __forceinline__ void issue_arm0(const RowMeta& m, const int* nc, const bool* valid,
                                           float* v0, float* v1)
{
    #pragma unroll
    for (int k = 0; k < 4; k++) if (valid[k]) v0[k] = __ldg(m.p0 + nc[k]);
    #pragma unroll
    for (int k = 0; k < 4; k++) if (valid[k]) v1[k] = __ldg(m.p0 + NCC + nc[k]);
}

// Combine: consume arm-0 values; arm-1 (if present, block-uniform) loaded here.
__device__ __forceinline__ void combine(const RowMeta& m, const int* nc, const bool* valid,
                                        const float* v0, const float* v1, float* cur)
{
    #pragma unroll
    for (int k = 0; k < 4; k++)
        cur[k] = m.w0 * (v0[k] * (1.0f - m.f0) + v1[k] * m.f0);
    if (m.two) {
        float u0[4], u1[4];
        #pragma unroll
        for (int k = 0; k < 4; k++) if (valid[k]) u0[k] = __ldg(m.p1 + nc[k]);
        #pragma unroll
        for (int k = 0; k < 4; k++) if (valid[k]) u1[k] = __ldg(m.p1 + NCC + nc[k]);
        #pragma unroll
        for (int k = 0; k < 4; k++)
            cur[k] += m.w1 * (u0[k] * (1.0f - m.f1) + u1[k] * m.f1);
    }
}

// One block per (b, 6-row strip); 1-row-deep software pipeline on x arm0 + noise.
__global__ void __launch_bounds__(BTHREADS, 3)
main_kernel(const float* __restrict__ x, const float* __restrict__ noise,
            const float* __restrict__ sp, float* __restrict__ out)
{
    const int t0 = blockIdx.x * RROWS;
    const int b  = blockIdx.y;
    const int row0 = b * NEW_T + t0;
    const int tid = threadIdx.x;

    const float* __restrict__ xb = x + (size_t)b * T_IN * NCC;

    bool valid[4];
    int  nc[4];
    #pragma unroll
    for (int k = 0; k < 4; k++) {
        nc[k] = tid + k * BTHREADS;
        valid[k] = (nc[k] < NCC);
    }

    const size_t sbase = (size_t)b * NCC;
    float spv[4];
    #pragma unroll
    for (int k = 0; k < 4; k++) if (valid[k]) spv[k] = __ldg(sp + sbase + nc[k]);

    // prev = x2(t0-1), unpipelined (once per block)
    float prev[4] = {0.f, 0.f, 0.f, 0.f};
    if (t0 > 0) {
        RowMeta mp = mkmeta(g_tab[row0 - 1], t0 - 1, xb, false);
        float pv0[4], pv1[4];
        issue_arm0(mp, nc, valid, pv0, pv1);
        combine(mp, nc, valid, pv0, pv1, prev);
    }

    // pipeline prologue: row 0 loads in flight
    RowMeta mc = mkmeta(g_tab[row0], t0, xb, t0 == 0);
    float va0[4], va1[4], nz[4];
    issue_arm0(mc, nc, valid, va0, va1);
    {
        const size_t rb = (size_t)row0 * NCC;
        #pragma unroll
        for (int k = 0; k < 4; k++) if (valid[k]) nz[k] = __ldg(noise + rb + nc[k]);
    }

    #pragma unroll
    for (int i = 0; i < RROWS; i++) {
        const int row = row0 + i;

        // stage i+1: issue next row's arm0 + noise loads before consuming row i
        RowMeta mn;
        float vb0[4], vb1[4], nz2[4];
        if (i + 1 < RROWS) {
            mn = mkmeta(g_tab[row + 1], t0 + i + 1, xb, false);
            issue_arm0(mn, nc, valid, vb0, vb1);
            const size_t rb = (size_t)(row + 1) * NCC;
            #pragma unroll
            for (int k = 0; k < 4; k++) if (valid[k]) nz2[k] = __ldg(noise + rb + nc[k]);
        }

        // consume row i
        float cur[4];
        combine(mc, nc, valid, va0, va1, cur);

        const size_t rbase = (size_t)row * NCC;
        const float jit = mc.jit;
        #pragma unroll
        for (int k = 0; k < 4; k++) {
            if (valid[k]) {
                float v = cur[k] + (cur[k] - prev[k]) * jit;   // jit==0 at t==0
                out[rbase + nc[k]] = v + nz[k] * 0.01f + spv[k] * 0.005f;
            }
        }

        #pragma unroll
        for (int k = 0; k < 4; k++) { prev[k] = cur[k]; va0[k] = vb0[k]; va1[k] = vb1[k]; nz[k] = nz2[k]; }
        mc = mn;
    }
}

extern "C" void kernel_launch(void* const* d_in, const int* in_sizes, int n_in,
                              void* d_out, int out_size)
{
    const float* x = nullptr; const void* mask = nullptr; const void* keep = nullptr;
    const float* bj = nullptr; const float* noise = nullptr; const float* sp = nullptr;

    for (int i = 0; i < n_in; i++) {
        switch (in_sizes[i]) {
            case NB * T_IN * NCC:  x     = (const float*)d_in[i]; break;
            case NB * T_IN:        mask  = d_in[i];               break;
            case NB * NEW_T:       keep  = d_in[i];               break;
            case NB * JF:          bj    = (const float*)d_in[i]; break;
            case NB * NEW_T * NCC: noise = (const float*)d_in[i]; break;
            case NB * NCC:         sp    = (const float*)d_in[i]; break;
            default: break;
        }
    }

    int write_mask = (out_size >= X_ELEMS + NB * NEW_T) ? 1 : 0;
    setup_kernel<<<NB, 512>>>(mask, keep, bj, (float*)d_out, write_mask);
    dim3 grid(NEW_T / RROWS, NB);   // 71 x 32
    main_kernel<<<grid, BTHREADS>>>(x, noise, sp, (float*)d_out);
}